// round 1
// baseline (speedup 1.0000x reference)
#include <cuda_runtime.h>
#include <cstddef>
#include <cstdint>

// Problem constants (from reference): N=50000, F=128, H=8, HID=8, CLS=40, E=1.6M
#define NMAX 50000
#define EMAX 1700000   // E + self loops head-room

// ---------------- static device scratch (no allocation allowed) ----------------
__device__ float g_hfeat[(size_t)NMAX * 64];
__device__ float g_actA [(size_t)NMAX * 64];
__device__ float g_actB [(size_t)NMAX * 64];
__device__ float g_s    [(size_t)NMAX * 16];   // packed per-node scores: [0..7]=src, [8..15]=dst
__device__ float g_alpha[(size_t)EMAX * 8];    // per-edge per-head attention weights
__device__ int   g_col  [EMAX];                // CSR column (src node) indices, grouped by dst
__device__ int   g_rowptr[NMAX + 1];
__device__ int   g_cursor[NMAX];
__device__ int   g_cnt   [NMAX];
__device__ float g_y    [(size_t)NMAX * 512];  // layer-5 pre-GEMM aggregate [N,8,64]
__device__ float g_Wfold[128 * 16];            // folded attention matrices  [K,16]
__device__ float g_Wp   [512 * 40];            // block-diag rearranged W5   [512,40]
__device__ float g_pre  [(size_t)NMAX * 40];   // layer-5 logits pre-softmax

// ---------------- CSR build ----------------
__global__ void k_init_cnt(int* cnt, int n) {
    int i = blockIdx.x * blockDim.x + threadIdx.x;
    if (i < n) cnt[i] = 1;                       // self loop
}

__global__ void k_hist(const int* __restrict__ dst, int* cnt, int E) {
    int i = blockIdx.x * blockDim.x + threadIdx.x;
    if (i < E) atomicAdd(&cnt[dst[i]], 1);
}

__global__ void k_scan(const int* __restrict__ cnt, int* rowptr, int* cursor, int n) {
    __shared__ int sm[1024];
    __shared__ int carry;
    int tid = threadIdx.x;
    if (tid == 0) carry = 0;
    __syncthreads();
    for (int base = 0; base < n; base += 1024) {
        int i = base + tid;
        int v = (i < n) ? cnt[i] : 0;
        sm[tid] = v;
        __syncthreads();
        for (int off = 1; off < 1024; off <<= 1) {
            int t = (tid >= off) ? sm[tid - off] : 0;
            __syncthreads();
            sm[tid] += t;
            __syncthreads();
        }
        int excl = carry + sm[tid] - v;
        if (i < n) { rowptr[i] = excl; cursor[i] = excl; }
        __syncthreads();
        if (tid == 0) carry += sm[1023];
        __syncthreads();
    }
    if (tid == 0) rowptr[n] = carry;
}

__global__ void k_scatter(const int* __restrict__ ei, int* cursor, int* col, int E, int n) {
    int i = blockIdx.x * blockDim.x + threadIdx.x;
    if (i < E) {
        int s = ei[i];
        int d = ei[E + i];
        int p = atomicAdd(&cursor[d], 1);
        col[p] = s;
    } else if (i < E + n) {
        int nd = i - E;
        int p = atomicAdd(&cursor[nd], 1);
        col[p] = nd;
    }
}

// ---------------- generic SGEMM: C[M,Nc] = A[M,K] @ B[K,Nc] ----------------
// BM=128, BN=64, BK=16, 256 threads, 8x4 microtile. K must be a multiple of 16.
__global__ __launch_bounds__(256) void k_gemm(
    const float* __restrict__ A, const float* __restrict__ B, float* __restrict__ C,
    int M, int Nc, int K)
{
    __shared__ float As[16][132];
    __shared__ float Bs[16][64];
    int tid = threadIdx.x;
    int bm = blockIdx.y * 128;
    int bn = blockIdx.x * 64;
    int tx = tid & 15;    // 16 col groups * 4
    int ty = tid >> 4;    // 16 row groups * 8
    float acc[8][4];
#pragma unroll
    for (int i = 0; i < 8; i++)
#pragma unroll
        for (int j = 0; j < 4; j++) acc[i][j] = 0.f;

    for (int k0 = 0; k0 < K; k0 += 16) {
        // load A tile (128x16) as 512 float4s, 2 per thread
#pragma unroll
        for (int it = 0; it < 2; it++) {
            int idx = tid + it * 256;
            int m  = idx >> 2;
            int kq = (idx & 3) * 4;
            int gm = bm + m;
            float4 v = make_float4(0.f, 0.f, 0.f, 0.f);
            if (gm < M) v = *(const float4*)(A + (size_t)gm * K + k0 + kq);
            As[kq + 0][m] = v.x;
            As[kq + 1][m] = v.y;
            As[kq + 2][m] = v.z;
            As[kq + 3][m] = v.w;
        }
        // load B tile (16x64), 4 scalars per thread
#pragma unroll
        for (int it = 0; it < 4; it++) {
            int idx = tid + it * 256;
            int kk = idx >> 6;
            int cc = idx & 63;
            int gc = bn + cc;
            float v = 0.f;
            if (gc < Nc) v = B[(size_t)(k0 + kk) * Nc + gc];
            Bs[kk][cc] = v;
        }
        __syncthreads();
#pragma unroll
        for (int kk = 0; kk < 16; kk++) {
            float4 a0 = *(const float4*)(&As[kk][ty * 8]);
            float4 a1 = *(const float4*)(&As[kk][ty * 8 + 4]);
            float4 b  = *(const float4*)(&Bs[kk][tx * 4]);
            float av[8] = {a0.x, a0.y, a0.z, a0.w, a1.x, a1.y, a1.z, a1.w};
            float bv[4] = {b.x, b.y, b.z, b.w};
#pragma unroll
            for (int i = 0; i < 8; i++)
#pragma unroll
                for (int j = 0; j < 4; j++) acc[i][j] += av[i] * bv[j];
        }
        __syncthreads();
    }
#pragma unroll
    for (int i = 0; i < 8; i++) {
        int gm = bm + ty * 8 + i;
        if (gm >= M) continue;
#pragma unroll
        for (int j = 0; j < 4; j++) {
            int gc = bn + tx * 4 + j;
            if (gc < Nc) C[(size_t)gm * Nc + gc] = acc[i][j];
        }
    }
}

// ---------------- attention-matrix fold: Wf[k, j] ----------------
// j<8 : sum_c W[k, h*C+c] * a_src[h,c];  j>=8 : a_dst. (h = j&7)
__global__ void k_fold(const float* __restrict__ W, const float* __restrict__ a_src,
                       const float* __restrict__ a_dst, float* __restrict__ Wf,
                       int K, int C)
{
    int idx = blockIdx.x * blockDim.x + threadIdx.x;
    if (idx >= K * 16) return;
    int k = idx >> 4;
    int j = idx & 15;
    int h = j & 7;
    const float* a = (j < 8) ? a_src : a_dst;
    float sum = 0.f;
    for (int c = 0; c < C; c++)
        sum += W[(size_t)k * 8 * C + h * C + c] * a[h * C + c];
    Wf[idx] = sum;
}

// ---------------- W5 rearrange to block-diag [512,40] ----------------
__global__ void k_wprime(const float* __restrict__ W5, float* __restrict__ Wp) {
    int idx = blockIdx.x * blockDim.x + threadIdx.x;
    if (idx >= 512 * 40) return;
    int kk = idx / 40;
    int c  = idx % 40;
    int h  = kk >> 6;
    int k  = kk & 63;
    Wp[idx] = W5[(size_t)k * 320 + h * 40 + c];
}

// ---------------- softmax stats + alpha (shared by both aggregators) ----------------
// One warp per node. Computes per-head max via online softmax, warp-reduces,
// then writes alpha[e*8+h] for every incoming edge.
__device__ __forceinline__ void softmax_alpha(
    const float* __restrict__ s, const int* __restrict__ colx,
    float* __restrict__ alpha, int node, int lane, int beg, int end)
{
    float sdv[8];
    const float* sd = s + (size_t)node * 16 + 8;
#pragma unroll
    for (int h = 0; h < 8; h++) sdv[h] = __ldg(sd + h);

    float m[8], l[8];
#pragma unroll
    for (int h = 0; h < 8; h++) { m[h] = -1e30f; l[h] = 0.f; }

    for (int e = beg + lane; e < end; e += 32) {
        int si = colx[e];
        const float4* sp = (const float4*)(s + (size_t)si * 16);
        float4 s0 = __ldg(sp);
        float4 s1 = __ldg(sp + 1);
        float ss[8] = {s0.x, s0.y, s0.z, s0.w, s1.x, s1.y, s1.z, s1.w};
#pragma unroll
        for (int h = 0; h < 8; h++) {
            float al = ss[h] + sdv[h];
            al = al > 0.f ? al : 0.2f * al;
            if (al > m[h]) { l[h] = l[h] * __expf(m[h] - al) + 1.f; m[h] = al; }
            else            l[h] += __expf(al - m[h]);
        }
    }
#pragma unroll
    for (int off = 16; off; off >>= 1) {
#pragma unroll
        for (int h = 0; h < 8; h++) {
            float om = __shfl_xor_sync(0xffffffffu, m[h], off);
            float ol = __shfl_xor_sync(0xffffffffu, l[h], off);
            float nm = fmaxf(m[h], om);
            l[h] = l[h] * __expf(m[h] - nm) + ol * __expf(om - nm);
            m[h] = nm;
        }
    }
    float inv[8];
#pragma unroll
    for (int h = 0; h < 8; h++) inv[h] = 1.f / (l[h] + 1e-16f);

    for (int e = beg + lane; e < end; e += 32) {
        int si = colx[e];
        const float4* sp = (const float4*)(s + (size_t)si * 16);
        float4 s0 = __ldg(sp);
        float4 s1 = __ldg(sp + 1);
        float ss[8] = {s0.x, s0.y, s0.z, s0.w, s1.x, s1.y, s1.z, s1.w};
        float av[8];
#pragma unroll
        for (int h = 0; h < 8; h++) {
            float al = ss[h] + sdv[h];
            al = al > 0.f ? al : 0.2f * al;
            av[h] = __expf(al - m[h]) * inv[h];
        }
        float4* ap = (float4*)(alpha + (size_t)e * 8);
        ap[0] = make_float4(av[0], av[1], av[2], av[3]);
        ap[1] = make_float4(av[4], av[5], av[6], av[7]);
    }
    __syncwarp();
}

// ---------------- concat-layer aggregation (layers 1-4), fused +bias +lrelu -----
__global__ __launch_bounds__(256) void k_agg_cat(
    const float* __restrict__ hfeat, const float* __restrict__ s,
    const int* __restrict__ rowptr, const int* __restrict__ colx,
    const float* __restrict__ bias, float* __restrict__ out,
    float* __restrict__ alpha, int n)
{
    int node = (blockIdx.x * blockDim.x + threadIdx.x) >> 5;
    if (node >= n) return;
    int lane = threadIdx.x & 31;
    int beg = rowptr[node], end = rowptr[node + 1];

    softmax_alpha(s, colx, alpha, node, lane, beg, end);

    // phase 3: lane -> (head h, channel pair cb)
    int h  = lane >> 2;
    int cb = (lane & 3) * 2;
    float a0 = 0.f, a1 = 0.f;
    for (int e = beg; e < end; e++) {
        int si = colx[e];
        float al = alpha[(size_t)e * 8 + h];                        // 4-lane broadcast
        float2 v = *(const float2*)(hfeat + (size_t)si * 64 + h * 8 + cb);
        a0 += al * v.x;
        a1 += al * v.y;
    }
    float r0 = a0 + __ldg(bias + h * 8 + cb);
    float r1 = a1 + __ldg(bias + h * 8 + cb + 1);
    r0 = r0 > 0.f ? r0 : 0.2f * r0;
    r1 = r1 > 0.f ? r1 : 0.2f * r1;
    size_t o = (size_t)node * 64 + h * 8 + cb;
    out[o]     = r0;
    out[o + 1] = r1;
}

// ---------------- layer-5 aggregation on input features: y[N,8,64] ----------------
__global__ __launch_bounds__(256) void k_agg_mean(
    const float* __restrict__ xin, const float* __restrict__ s,
    const int* __restrict__ rowptr, const int* __restrict__ colx,
    float* __restrict__ y, float* __restrict__ alpha, int n)
{
    int node = (blockIdx.x * blockDim.x + threadIdx.x) >> 5;
    if (node >= n) return;
    int lane = threadIdx.x & 31;
    int beg = rowptr[node], end = rowptr[node + 1];

    softmax_alpha(s, colx, alpha, node, lane, beg, end);

    int kb = lane * 2;
    float acc[8][2];
#pragma unroll
    for (int h = 0; h < 8; h++) { acc[h][0] = 0.f; acc[h][1] = 0.f; }

    for (int e = beg; e < end; e++) {
        int si = colx[e];
        float2 v = *(const float2*)(xin + (size_t)si * 64 + kb);
        const float4* ap = (const float4*)(alpha + (size_t)e * 8);  // broadcast
        float4 q0 = ap[0];
        float4 q1 = ap[1];
        float av[8] = {q0.x, q0.y, q0.z, q0.w, q1.x, q1.y, q1.z, q1.w};
#pragma unroll
        for (int h = 0; h < 8; h++) {
            acc[h][0] += av[h] * v.x;
            acc[h][1] += av[h] * v.y;
        }
    }
#pragma unroll
    for (int h = 0; h < 8; h++) {
        size_t o = (size_t)node * 512 + h * 64 + kb;
        y[o]     = acc[h][0];
        y[o + 1] = acc[h][1];
    }
}

// ---------------- final: mean(/8) + b5 + log_softmax ----------------
__global__ __launch_bounds__(256) void k_lsm(
    const float* __restrict__ pre, const float* __restrict__ b5,
    float* __restrict__ out, int n)
{
    int node = (blockIdx.x * blockDim.x + threadIdx.x) >> 5;
    if (node >= n) return;
    int lane = threadIdx.x & 31;
    float v0 = pre[(size_t)node * 40 + lane] * 0.125f + __ldg(b5 + lane);
    float v1 = -1e30f;
    if (lane < 8) v1 = pre[(size_t)node * 40 + 32 + lane] * 0.125f + __ldg(b5 + 32 + lane);
    float mx = fmaxf(v0, v1);
#pragma unroll
    for (int off = 16; off; off >>= 1) mx = fmaxf(mx, __shfl_xor_sync(0xffffffffu, mx, off));
    float sum = __expf(v0 - mx) + (lane < 8 ? __expf(v1 - mx) : 0.f);
#pragma unroll
    for (int off = 16; off; off >>= 1) sum += __shfl_xor_sync(0xffffffffu, sum, off);
    float lse = mx + __logf(sum);
    out[(size_t)node * 40 + lane] = v0 - lse;
    if (lane < 8) out[(size_t)node * 40 + 32 + lane] = v1 - lse;
}

// ---------------- host ----------------
static void* sym(const void* s) {
    void* p = nullptr;
    cudaGetSymbolAddress(&p, s);
    return p;
}

extern "C" void kernel_launch(void* const* d_in, const int* in_sizes, int n_in,
                              void* d_out, int out_size)
{
    const float* x   = (const float*)d_in[0];
    const int*   ei  = (const int*)d_in[1];
    const float* Ws[5]  = {(const float*)d_in[2],  (const float*)d_in[6],
                           (const float*)d_in[10], (const float*)d_in[14],
                           (const float*)d_in[18]};
    const float* asv[5] = {(const float*)d_in[3],  (const float*)d_in[7],
                           (const float*)d_in[11], (const float*)d_in[15],
                           (const float*)d_in[19]};
    const float* adv[5] = {(const float*)d_in[4],  (const float*)d_in[8],
                           (const float*)d_in[12], (const float*)d_in[16],
                           (const float*)d_in[20]};
    const float* bs[5]  = {(const float*)d_in[5],  (const float*)d_in[9],
                           (const float*)d_in[13], (const float*)d_in[17],
                           (const float*)d_in[21]};

    int n    = in_sizes[0] / 128;
    int E    = in_sizes[1] / 2;

    float* hfeat  = (float*)sym(g_hfeat);
    float* actA   = (float*)sym(g_actA);
    float* actB   = (float*)sym(g_actB);
    float* sbuf   = (float*)sym(g_s);
    float* alpha  = (float*)sym(g_alpha);
    int*   col    = (int*)  sym(g_col);
    int*   rowptr = (int*)  sym(g_rowptr);
    int*   cursor = (int*)  sym(g_cursor);
    int*   cnt    = (int*)  sym(g_cnt);
    float* ybuf   = (float*)sym(g_y);
    float* Wfold  = (float*)sym(g_Wfold);
    float* Wp     = (float*)sym(g_Wp);
    float* pre    = (float*)sym(g_pre);

    // ---- CSR build (dst-grouped) ----
    k_init_cnt<<<(n + 255) / 256, 256>>>(cnt, n);
    k_hist<<<(E + 255) / 256, 256>>>(ei + E, cnt, E);
    k_scan<<<1, 1024>>>(cnt, rowptr, cursor, n);
    k_scatter<<<(E + n + 255) / 256, 256>>>(ei, cursor, col, E, n);

    int warpBlocks = (n + 7) / 8;   // 8 warps (one node each) per 256-thread block

    // ---- layers 1..4 (concat, lrelu) ----
    const float* cur = x;
    int K = 128;
    float* acts[2] = {actA, actB};
    for (int L = 0; L < 4; L++) {
        k_fold<<<(K * 16 + 255) / 256, 256>>>(Ws[L], asv[L], adv[L], Wfold, K, 8);
        {
            dim3 g((16 + 63) / 64, (n + 127) / 128);
            k_gemm<<<g, 256>>>(cur, Wfold, sbuf, n, 16, K);
        }
        {
            dim3 g((64 + 63) / 64, (n + 127) / 128);
            k_gemm<<<g, 256>>>(cur, Ws[L], hfeat, n, 64, K);
        }
        k_agg_cat<<<warpBlocks, 256>>>(hfeat, sbuf, rowptr, col, bs[L],
                                       acts[L & 1], alpha, n);
        cur = acts[L & 1];
        K = 64;
    }

    // ---- layer 5 (mean over heads), restructured: aggregate x4, GEMM after ----
    k_fold<<<(64 * 16 + 255) / 256, 256>>>(Ws[4], asv[4], adv[4], Wfold, 64, 40);
    {
        dim3 g(1, (n + 127) / 128);
        k_gemm<<<g, 256>>>(cur, Wfold, sbuf, n, 16, 64);
    }
    k_agg_mean<<<warpBlocks, 256>>>(cur, sbuf, rowptr, col, ybuf, alpha, n);
    k_wprime<<<(512 * 40 + 255) / 256, 256>>>(Ws[4], Wp);
    {
        dim3 g(1, (n + 127) / 128);
        k_gemm<<<g, 256>>>(ybuf, Wp, pre, n, 40, 512);
    }
    k_lsm<<<warpBlocks, 256>>>(pre, bs[4], (float*)d_out, n);
}